// round 10
// baseline (speedup 1.0000x reference)
#include <cuda_runtime.h>

typedef unsigned long long u64;

#define BATCH 32
#define NSEQ  2048
#define F     32
#define SPLITS 64
#define ROWS1 32                 // rows per kernel-1 block
#define ROWS2 32                 // rows per kernel-2 block
#define INV_N (1.0f / 2048.0f)

// Scratch (fully overwritten every launch -> deterministic)
__device__ float g_Mpart[BATCH * SPLITS * F * F];
__device__ float g_M2[BATCH * F * F];          // (M @ w_r) * invN
__device__ float g_psi[BATCH * NSEQ * F];
__device__ float g_u[BATCH * NSEQ * F];
__device__ float g_diag[BATCH * NSEQ];

// ---- packed f32x2 helpers ----
__device__ __forceinline__ u64 pk2(float a, float b) {
    u64 r; asm("mov.b64 %0,{%1,%2};" : "=l"(r) : "f"(a), "f"(b)); return r;
}
__device__ __forceinline__ float2 up2(u64 v) {
    float2 f; asm("mov.b64 {%0,%1},%2;" : "=f"(f.x), "=f"(f.y) : "l"(v)); return f;
}
__device__ __forceinline__ u64 ffma2(u64 a, u64 b, u64 c) {
    u64 d; asm("fma.rn.f32x2 %0,%1,%2,%3;" : "=l"(d) : "l"(a), "l"(b), "l"(c)); return d;
}
__device__ __forceinline__ u64 add2(u64 a, u64 b) {
    u64 d; asm("add.rn.f32x2 %0,%1,%2;" : "=l"(d) : "l"(a), "l"(b)); return d;
}

// ---------------------------------------------------------------------------
// Kernel 1: per 32-row slice: psi/phi/u (4 thr/row, warp = 32 rows x one
// 8-feature quarter -> warp-uniform weight LDS), diag, partial M.
// Persists psi, u (relu'd), diag.
// ---------------------------------------------------------------------------
__global__ __launch_bounds__(128) void k_partialM(
    const float* __restrict__ x,
    const float* __restrict__ w_psi, const float* __restrict__ b_psi,
    const float* __restrict__ w_phi, const float* __restrict__ b_phi,
    const float* __restrict__ w_u,   const float* __restrict__ b_u)
{
    __shared__ alignas(16) float ws_psi[F * F], ws_phi[F * F], ws_u[F * F];
    __shared__ alignas(16) float bs_psi[F], bs_phi[F], bs_u[F];
    __shared__ alignas(16) float phi_s[ROWS1 * 36];
    __shared__ alignas(16) float u_s[ROWS1 * 36];
    __shared__ float ds[4][ROWS1];

    const int b     = blockIdx.x;
    const int split = blockIdx.y;
    const int t     = threadIdx.x;

#pragma unroll
    for (int i = t; i < 256; i += 128) {
        ((float4*)ws_psi)[i] = ((const float4*)w_psi)[i];
        ((float4*)ws_phi)[i] = ((const float4*)w_phi)[i];
        ((float4*)ws_u  )[i] = ((const float4*)w_u  )[i];
    }
    if (t < F) { bs_psi[t] = b_psi[t]; bs_phi[t] = b_phi[t]; bs_u[t] = b_u[t]; }
    __syncthreads();

    // ---- Phase A: lane r = t&31 = row, warp qq = t>>5 = feature quarter
    const int r    = t & 31;
    const int qq   = t >> 5;
    const int hoff = qq * 8;                 // features [hoff, hoff+8)
    const int row  = split * ROWS1 + r;
    const size_t grow = ((size_t)b * NSEQ + row) * F + hoff;

    const float4* xr = (const float4*)(x + ((size_t)b * NSEQ + row) * F);
    float xv[F];
#pragma unroll
    for (int i = 0; i < 8; i++) {
        float4 v = xr[i];
        xv[4*i+0] = v.x; xv[4*i+1] = v.y; xv[4*i+2] = v.z; xv[4*i+3] = v.w;
    }

    u64 ps[4], ph[4], uv[4];
#pragma unroll
    for (int i = 0; i < 4; i++) {
        ps[i] = ((const u64*)bs_psi)[qq * 4 + i];
        ph[i] = ((const u64*)bs_phi)[qq * 4 + i];
        uv[i] = ((const u64*)bs_u  )[qq * 4 + i];
    }
#pragma unroll
    for (int k = 0; k < F; k++) {
        const u64 xk2 = pk2(xv[k], xv[k]);
        const ulonglong2* wp = (const ulonglong2*)(ws_psi + k * F + hoff);
        const ulonglong2* wf = (const ulonglong2*)(ws_phi + k * F + hoff);
        const ulonglong2* wu = (const ulonglong2*)(ws_u   + k * F + hoff);
        {
            ulonglong2 a = wp[0];            // warp-uniform LDS.128
            ps[0] = ffma2(xk2, a.x, ps[0]); ps[1] = ffma2(xk2, a.y, ps[1]);
        }
        {
            ulonglong2 a = wp[1];
            ps[2] = ffma2(xk2, a.x, ps[2]); ps[3] = ffma2(xk2, a.y, ps[3]);
        }
        {
            ulonglong2 a = wf[0];
            ph[0] = ffma2(xk2, a.x, ph[0]); ph[1] = ffma2(xk2, a.y, ph[1]);
        }
        {
            ulonglong2 a = wf[1];
            ph[2] = ffma2(xk2, a.x, ph[2]); ph[3] = ffma2(xk2, a.y, ph[3]);
        }
        {
            ulonglong2 a = wu[0];
            uv[0] = ffma2(xk2, a.x, uv[0]); uv[1] = ffma2(xk2, a.y, uv[1]);
        }
        {
            ulonglong2 a = wu[1];
            uv[2] = ffma2(xk2, a.x, uv[2]); uv[3] = ffma2(xk2, a.y, uv[3]);
        }
    }

    // relu + diag partial
    u64 dac = 0ull;
#pragma unroll
    for (int i = 0; i < 4; i++) {
        float2 tu = up2(uv[i]);
        uv[i] = pk2(fmaxf(tu.x, 0.0f), fmaxf(tu.y, 0.0f));
        dac = ffma2(ps[i], ph[i], dac);
    }
    float2 dd = up2(dac);
    ds[qq][r] = dd.x + dd.y;

    // persist psi, u (8 floats = 2x STG.128 each, fully coalesced per warp)
#pragma unroll
    for (int q = 0; q < 2; q++) {
        float2 p0 = up2(ps[2*q+0]), p1 = up2(ps[2*q+1]);
        ((float4*)(g_psi + grow))[q] = make_float4(p0.x, p0.y, p1.x, p1.y);
        float2 v0 = up2(uv[2*q+0]), v1 = up2(uv[2*q+1]);
        ((float4*)(g_u + grow))[q]   = make_float4(v0.x, v0.y, v1.x, v1.y);
    }

    // stage phi, u for phase B
    u64* prow = (u64*)(phi_s + r * 36 + hoff);
    u64* urow = (u64*)(u_s   + r * 36 + hoff);
#pragma unroll
    for (int i = 0; i < 4; i++) { prow[i] = ph[i]; urow[i] = uv[i]; }
    __syncthreads();

    if (t < ROWS1)
        g_diag[(size_t)b * NSEQ + split * ROWS1 + t] =
            ds[0][t] + ds[1][t] + ds[2][t] + ds[3][t];

    // ---- Phase B: warp w owns f1 in [8w,8w+8), lane = f2 ----
    const int lane = t & 31;
    const int w    = t >> 5;
    u64 acc2[4] = {0ull, 0ull, 0ull, 0ull};

#pragma unroll 4
    for (int j = 0; j < ROWS1; j++) {
        const float uj = u_s[j * 36 + lane];
        const u64 uj2 = pk2(uj, uj);
        const ulonglong2* pr = (const ulonglong2*)(phi_s + j * 36 + w * 8);
        ulonglong2 p0 = pr[0], p1 = pr[1];
        acc2[0] = ffma2(uj2, p0.x, acc2[0]);
        acc2[1] = ffma2(uj2, p0.y, acc2[1]);
        acc2[2] = ffma2(uj2, p1.x, acc2[2]);
        acc2[3] = ffma2(uj2, p1.y, acc2[3]);
    }

    float* mp = g_Mpart + ((size_t)(b * SPLITS + split)) * F * F;
#pragma unroll
    for (int q = 0; q < 4; q++) {
        float2 v = up2(acc2[q]);
        mp[(w * 8 + 2*q + 0) * F + lane] = v.x;
        mp[(w * 8 + 2*q + 1) * F + lane] = v.y;
    }
}

// ---------------------------------------------------------------------------
// Kernel 1b: reduce SPLITS partials -> M, then M2 = (M @ w_r) * invN
// ---------------------------------------------------------------------------
__global__ __launch_bounds__(256) void k_reduceM(const float* __restrict__ w_r)
{
    __shared__ float Ms[F * F];
    __shared__ float wrs[F * F];
    const int b = blockIdx.x;
    const int t = threadIdx.x;

#pragma unroll
    for (int e = t; e < F * F; e += 256) {
        float s = 0.0f;
        const float* mp = g_Mpart + (size_t)b * SPLITS * F * F + e;
#pragma unroll
        for (int sp = 0; sp < SPLITS; sp++) s += mp[sp * F * F];
        Ms[e] = s;
        wrs[e] = w_r[e];
    }
    __syncthreads();

    const int k  = t >> 3;
    const int f0 = (t & 7) * 4;
    float a0 = 0.f, a1 = 0.f, a2 = 0.f, a3 = 0.f;
#pragma unroll
    for (int m = 0; m < F; m++) {
        const float mv = Ms[k * F + m];
        float4 w4 = *(const float4*)(wrs + m * F + f0);
        a0 += mv * w4.x; a1 += mv * w4.y; a2 += mv * w4.z; a3 += mv * w4.w;
    }
    float4* o4 = (float4*)(g_M2 + (size_t)b * F * F + k * F + f0);
    *o4 = make_float4(a0 * INV_N, a1 * INV_N, a2 * INV_N, a3 * INV_N);
}

// ---------------------------------------------------------------------------
// Kernel 2: out = x + psi @ M2 - (diag*invN) * (u @ w_r)
// 128 thr, 32 rows, 4 thr/row (warp = 32 rows x one 8-feature quarter).
// ---------------------------------------------------------------------------
__global__ __launch_bounds__(128) void k_main(
    const float* __restrict__ x,
    const float* __restrict__ w_r,
    float* __restrict__ out)
{
    __shared__ alignas(16) float wrs[F * F];
    __shared__ alignas(16) float m2s[F * F];
    __shared__ alignas(16) float psi_s[ROWS2 * 36];
    __shared__ alignas(16) float u_s[ROWS2 * 36];
    __shared__ float dia_s[ROWS2];

    const int b     = blockIdx.x >> 6;          // 64 chunks per batch
    const int chunk = blockIdx.x & 63;
    const int t     = threadIdx.x;
    const int r     = t & 31;
    const int qq    = t >> 5;
    const int hoff  = qq * 8;
    const size_t rowbase = (size_t)b * NSEQ + chunk * ROWS2;

#pragma unroll
    for (int i = t; i < 256; i += 128) {
        ((float4*)wrs)[i] = ((const float4*)w_r)[i];
        ((float4*)m2s)[i] = ((const float4*)(g_M2 + (size_t)b * F * F))[i];
    }
    // stage psi, u tiles (256 float4 each -> 2 per thread)
#pragma unroll
    for (int i = t; i < 256; i += 128) {
        int row = i >> 3, c = (i & 7) << 2;
        float4 p = ((const float4*)(g_psi + rowbase * F))[i];
        float4 v = ((const float4*)(g_u   + rowbase * F))[i];
        *(float4*)(psi_s + row * 36 + c) = p;
        *(float4*)(u_s   + row * 36 + c) = v;
    }
    if (t < ROWS2) dia_s[t] = g_diag[rowbase + t];
    __syncthreads();

    // ---- at = psi @ M2 ; uw = u @ w_r (8 features each) ----
    u64 at[4] = {0,0,0,0};
    u64 uw[4] = {0,0,0,0};
#pragma unroll
    for (int k = 0; k < F; k++) {
        const float pkv = psi_s[r * 36 + k];
        const float ukv = u_s  [r * 36 + k];
        const u64 pk2v = pk2(pkv, pkv);
        const u64 uk2v = pk2(ukv, ukv);
        const ulonglong2* mm = (const ulonglong2*)(m2s + k * F + hoff);
        const ulonglong2* wr = (const ulonglong2*)(wrs + k * F + hoff);
        {
            ulonglong2 a = mm[0];
            at[0] = ffma2(pk2v, a.x, at[0]); at[1] = ffma2(pk2v, a.y, at[1]);
        }
        {
            ulonglong2 a = mm[1];
            at[2] = ffma2(pk2v, a.x, at[2]); at[3] = ffma2(pk2v, a.y, at[3]);
        }
        {
            ulonglong2 a = wr[0];
            uw[0] = ffma2(uk2v, a.x, uw[0]); uw[1] = ffma2(uk2v, a.y, uw[1]);
        }
        {
            ulonglong2 a = wr[1];
            uw[2] = ffma2(uk2v, a.x, uw[2]); uw[3] = ffma2(uk2v, a.y, uw[3]);
        }
    }

    // ---- out = x + at - s*uw ----
    const float s = dia_s[r] * INV_N;
    const size_t g = (rowbase + r) * F + hoff;
    const u64 ns2 = pk2(-s, -s);
#pragma unroll
    for (int q = 0; q < 2; q++) {
        float4 xq = ((const float4*)(x + g))[q];
        u64 o0 = add2(ffma2(ns2, uw[2*q+0], at[2*q+0]), pk2(xq.x, xq.y));
        u64 o1 = add2(ffma2(ns2, uw[2*q+1], at[2*q+1]), pk2(xq.z, xq.w));
        float2 a0 = up2(o0), a1 = up2(o1);
        ((float4*)(out + g))[q] = make_float4(a0.x, a0.y, a1.x, a1.y);
    }
}

// ---------------------------------------------------------------------------
extern "C" void kernel_launch(void* const* d_in, const int* in_sizes, int n_in,
                              void* d_out, int out_size)
{
    const float* x     = (const float*)d_in[0];
    const float* w_psi = (const float*)d_in[1];
    const float* b_psi = (const float*)d_in[2];
    const float* w_phi = (const float*)d_in[3];
    const float* b_phi = (const float*)d_in[4];
    const float* w_u   = (const float*)d_in[5];
    const float* b_u   = (const float*)d_in[6];
    const float* w_r   = (const float*)d_in[7];
    float* out = (float*)d_out;

    dim3 g1(BATCH, SPLITS);
    k_partialM<<<g1, 128>>>(x, w_psi, b_psi, w_phi, b_phi, w_u, b_u);
    k_reduceM<<<BATCH, 256>>>(w_r);
    k_main<<<BATCH * 64, 128>>>(x, w_r, out);
}

// round 12
// speedup vs baseline: 1.0367x; 1.0367x over previous
#include <cuda_runtime.h>

typedef unsigned long long u64;

#define BATCH 32
#define NSEQ  2048
#define F     32
#define SPLITS 32
#define ROWS1 64
#define INV_N (1.0f / 2048.0f)

// Scratch (fully overwritten every launch -> deterministic)
__device__ float g_Mpart[BATCH * SPLITS * F * F];
__device__ float g_M3[BATCH * F * F];   // W_psi @ (M @ w_r * invN)
__device__ float g_b3[BATCH * F];       // b_psi @ M2
__device__ float g_u[BATCH * NSEQ * F];
__device__ float g_G[F * F];            // W_psi @ W_phi^T
__device__ float g_v[F];                // W_psi@b_phi + W_phi@b_psi
__device__ float g_c[1];                // b_psi . b_phi

// ---- packed f32x2 helpers ----
__device__ __forceinline__ u64 pk2(float a, float b) {
    u64 r; asm("mov.b64 %0,{%1,%2};" : "=l"(r) : "f"(a), "f"(b)); return r;
}
__device__ __forceinline__ float2 up2(u64 v) {
    float2 f; asm("mov.b64 {%0,%1},%2;" : "=f"(f.x), "=f"(f.y) : "l"(v)); return f;
}
__device__ __forceinline__ u64 ffma2(u64 a, u64 b, u64 c) {
    u64 d; asm("fma.rn.f32x2 %0,%1,%2,%3;" : "=l"(d) : "l"(a), "l"(b), "l"(c)); return d;
}
__device__ __forceinline__ u64 add2(u64 a, u64 b) {
    u64 d; asm("add.rn.f32x2 %0,%1,%2;" : "=l"(d) : "l"(a), "l"(b)); return d;
}

// ---------------------------------------------------------------------------
// k_pre: G = W_psi @ W_phi^T, v = W_psi@b_phi + W_phi@b_psi, c = b_psi.b_phi
// ---------------------------------------------------------------------------
__global__ __launch_bounds__(256) void k_pre(
    const float* __restrict__ w_psi, const float* __restrict__ b_psi,
    const float* __restrict__ w_phi, const float* __restrict__ b_phi)
{
    __shared__ alignas(16) float wps[F * F], wfs[F * F];
    __shared__ float bps[F], bfs[F];
    const int t = threadIdx.x;

    ((float4*)wps)[t] = ((const float4*)w_psi)[t];
    ((float4*)wfs)[t] = ((const float4*)w_phi)[t];
    if (t < F) { bps[t] = b_psi[t]; bfs[t] = b_phi[t]; }
    __syncthreads();

    const int k1 = t >> 3;
    const int c0 = (t & 7) * 4;
    float a0 = 0.f, a1 = 0.f, a2 = 0.f, a3 = 0.f;
#pragma unroll
    for (int f = 0; f < F; f++) {
        const float pw = wps[k1 * F + f];
        a0 += pw * wfs[(c0 + 0) * F + f];
        a1 += pw * wfs[(c0 + 1) * F + f];
        a2 += pw * wfs[(c0 + 2) * F + f];
        a3 += pw * wfs[(c0 + 3) * F + f];
    }
    *(float4*)(g_G + k1 * F + c0) = make_float4(a0, a1, a2, a3);

    if (t < F) {
        float s = 0.f;
#pragma unroll
        for (int f = 0; f < F; f++)
            s += wps[t * F + f] * bfs[f] + wfs[t * F + f] * bps[f];
        g_v[t] = s;
    }
    if (t == 0) {
        float s = 0.f;
#pragma unroll
        for (int f = 0; f < F; f++) s += bps[f] * bfs[f];
        g_c[0] = s;
    }
}

// ---------------------------------------------------------------------------
// Kernel 1 (R8-proven shape): phi,u (2 thr/row x 16 feats), partial M.
// Persists relu'd u.
// ---------------------------------------------------------------------------
__global__ __launch_bounds__(128) void k_partialM(
    const float* __restrict__ x,
    const float* __restrict__ w_phi, const float* __restrict__ b_phi,
    const float* __restrict__ w_u,   const float* __restrict__ b_u)
{
    __shared__ alignas(16) float ws_phi[F * F], ws_u[F * F];
    __shared__ alignas(16) float bs_phi[F], bs_u[F];
    __shared__ alignas(16) float phi_s[ROWS1 * 36];
    __shared__ alignas(16) float u_s[ROWS1 * 36];

    const int b     = blockIdx.x;
    const int split = blockIdx.y;
    const int t     = threadIdx.x;

#pragma unroll
    for (int i = t; i < 256; i += 128) {
        ((float4*)ws_phi)[i] = ((const float4*)w_phi)[i];
        ((float4*)ws_u  )[i] = ((const float4*)w_u  )[i];
    }
    if (t < F) { bs_phi[t] = b_phi[t]; bs_u[t] = b_u[t]; }
    __syncthreads();

    // ---- Phase A: row r = t&63, half h = t>>6 -> features [h*16, h*16+16)
    const int r    = t & 63;
    const int h    = t >> 6;
    const int hoff = h * 16;
    const int row  = split * ROWS1 + r;
    const size_t grow = ((size_t)b * NSEQ + row) * F + hoff;

    const float4* xr = (const float4*)(x + ((size_t)b * NSEQ + row) * F);
    float xv[F];
#pragma unroll
    for (int i = 0; i < 8; i++) {
        float4 v = xr[i];
        xv[4*i+0] = v.x; xv[4*i+1] = v.y; xv[4*i+2] = v.z; xv[4*i+3] = v.w;
    }

    u64 ph[8], uv[8];
#pragma unroll
    for (int i = 0; i < 8; i++) {
        ph[i] = ((const u64*)bs_phi)[h * 8 + i];
        uv[i] = ((const u64*)bs_u  )[h * 8 + i];
    }
#pragma unroll
    for (int k = 0; k < F; k++) {
        const u64 xk2 = pk2(xv[k], xv[k]);
        const ulonglong2* wf = (const ulonglong2*)(ws_phi + k * F + hoff);
        const ulonglong2* wu = (const ulonglong2*)(ws_u   + k * F + hoff);
#pragma unroll
        for (int q = 0; q < 4; q++) {
            ulonglong2 a = wf[q];
            ph[2*q+0] = ffma2(xk2, a.x, ph[2*q+0]);
            ph[2*q+1] = ffma2(xk2, a.y, ph[2*q+1]);
        }
#pragma unroll
        for (int q = 0; q < 4; q++) {
            ulonglong2 a = wu[q];
            uv[2*q+0] = ffma2(xk2, a.x, uv[2*q+0]);
            uv[2*q+1] = ffma2(xk2, a.y, uv[2*q+1]);
        }
    }
    // relu
#pragma unroll
    for (int i = 0; i < 8; i++) {
        float2 tu = up2(uv[i]);
        uv[i] = pk2(fmaxf(tu.x, 0.0f), fmaxf(tu.y, 0.0f));
    }

    // persist u (4x STG.128, coalesced)
#pragma unroll
    for (int q = 0; q < 4; q++) {
        float2 v0 = up2(uv[2*q+0]), v1 = up2(uv[2*q+1]);
        ((float4*)(g_u + grow))[q] = make_float4(v0.x, v0.y, v1.x, v1.y);
    }

    // stage phi, u for phase B
    u64* prow = (u64*)(phi_s + r * 36 + hoff);
    u64* urow = (u64*)(u_s   + r * 36 + hoff);
#pragma unroll
    for (int i = 0; i < 8; i++) { prow[i] = ph[i]; urow[i] = uv[i]; }
    __syncthreads();

    // ---- Phase B: warp w owns f1 in [8w,8w+8), lane = f2
    const int lane = t & 31;
    const int w    = t >> 5;
    u64 acc2[4] = {0ull, 0ull, 0ull, 0ull};

#pragma unroll 4
    for (int j = 0; j < ROWS1; j++) {
        const float uj = u_s[j * 36 + lane];
        const u64 uj2 = pk2(uj, uj);
        const ulonglong2* pr = (const ulonglong2*)(phi_s + j * 36 + w * 8);
        ulonglong2 p0 = pr[0], p1 = pr[1];
        acc2[0] = ffma2(uj2, p0.x, acc2[0]);
        acc2[1] = ffma2(uj2, p0.y, acc2[1]);
        acc2[2] = ffma2(uj2, p1.x, acc2[2]);
        acc2[3] = ffma2(uj2, p1.y, acc2[3]);
    }

    float* mp = g_Mpart + ((size_t)(b * SPLITS + split)) * F * F;
#pragma unroll
    for (int q = 0; q < 4; q++) {
        float2 v = up2(acc2[q]);
        mp[(w * 8 + 2*q + 0) * F + lane] = v.x;
        mp[(w * 8 + 2*q + 1) * F + lane] = v.y;
    }
}

// ---------------------------------------------------------------------------
// k_reduceM: M = sum partials; M2 = M@w_r*invN; M3 = W_psi@M2; b3 = b_psi@M2
// ---------------------------------------------------------------------------
__global__ __launch_bounds__(256) void k_reduceM(
    const float* __restrict__ w_r,
    const float* __restrict__ w_psi, const float* __restrict__ b_psi)
{
    __shared__ float Ms[F * F], wrs[F * F], m2s[F * F], wps[F * F];
    __shared__ float bps[F];
    const int b = blockIdx.x;
    const int t = threadIdx.x;

#pragma unroll
    for (int e = t; e < F * F; e += 256) {
        float s = 0.0f;
        const float* mp = g_Mpart + (size_t)b * SPLITS * F * F + e;
#pragma unroll
        for (int sp = 0; sp < SPLITS; sp++) s += mp[sp * F * F];
        Ms[e]  = s;
        wrs[e] = w_r[e];
        wps[e] = w_psi[e];
    }
    if (t < F) bps[t] = b_psi[t];
    __syncthreads();

    const int k  = t >> 3;
    const int f0 = (t & 7) * 4;
    {
        float a0 = 0.f, a1 = 0.f, a2 = 0.f, a3 = 0.f;
#pragma unroll
        for (int m = 0; m < F; m++) {
            const float mv = Ms[k * F + m];
            float4 w4 = *(const float4*)(wrs + m * F + f0);
            a0 += mv * w4.x; a1 += mv * w4.y; a2 += mv * w4.z; a3 += mv * w4.w;
        }
        *(float4*)(m2s + k * F + f0) =
            make_float4(a0 * INV_N, a1 * INV_N, a2 * INV_N, a3 * INV_N);
    }
    __syncthreads();

    {
        float a0 = 0.f, a1 = 0.f, a2 = 0.f, a3 = 0.f;
#pragma unroll
        for (int m = 0; m < F; m++) {
            const float wv = wps[k * F + m];
            float4 m4 = *(const float4*)(m2s + m * F + f0);
            a0 += wv * m4.x; a1 += wv * m4.y; a2 += wv * m4.z; a3 += wv * m4.w;
        }
        *(float4*)(g_M3 + (size_t)b * F * F + k * F + f0) =
            make_float4(a0, a1, a2, a3);
    }
    if (t < 8) {
        const int f = t * 4;
        float a0 = 0.f, a1 = 0.f, a2 = 0.f, a3 = 0.f;
#pragma unroll
        for (int m = 0; m < F; m++) {
            const float bv = bps[m];
            float4 m4 = *(const float4*)(m2s + m * F + f);
            a0 += bv * m4.x; a1 += bv * m4.y; a2 += bv * m4.z; a3 += bv * m4.w;
        }
        *(float4*)(g_b3 + (size_t)b * F + f) = make_float4(a0, a1, a2, a3);
    }
}

// ---------------------------------------------------------------------------
// Kernel 2: per-row, sync-free after preamble. 1 thr/row, 128 rows/block.
//   tt = x@G; diag = tt.x + x.v + c
//   o  = x + (x@M3 + b3)
//   uw = u@w_r;  out = o - (diag*invN)*uw
// ---------------------------------------------------------------------------
__global__ __launch_bounds__(128) void k_main(
    const float* __restrict__ x,
    const float* __restrict__ w_r,
    float* __restrict__ out)
{
    __shared__ alignas(16) float wrs[F * F], m3s[F * F], Gs[F * F];
    __shared__ alignas(16) float b3s[F], vs[F];
    __shared__ float cshared;

    const int b     = blockIdx.x >> 4;          // 16 chunks of 128 rows
    const int chunk = blockIdx.x & 15;
    const int t     = threadIdx.x;

#pragma unroll
    for (int i = t; i < 256; i += 128) {
        ((float4*)wrs)[i] = ((const float4*)w_r)[i];
        ((float4*)m3s)[i] = ((const float4*)(g_M3 + (size_t)b * F * F))[i];
        ((float4*)Gs )[i] = ((const float4*)g_G)[i];
    }
    if (t < F) { b3s[t] = g_b3[(size_t)b * F + t]; vs[t] = g_v[t]; }
    if (t == 0) cshared = g_c[0];
    __syncthreads();

    const size_t rowg = (size_t)b * NSEQ + chunk * 128 + t;
    const size_t gx   = rowg * F;

    // x row -> regs
    float xv[F];
#pragma unroll
    for (int i = 0; i < 8; i++) {
        float4 v = ((const float4*)(x + gx))[i];
        xv[4*i+0] = v.x; xv[4*i+1] = v.y; xv[4*i+2] = v.z; xv[4*i+3] = v.w;
    }

    // ---- pass 1: tt = x @ G ----
    u64 tt[16];
#pragma unroll
    for (int i = 0; i < 16; i++) tt[i] = 0ull;
#pragma unroll
    for (int k = 0; k < F; k++) {
        const u64 xk2 = pk2(xv[k], xv[k]);
        const ulonglong2* gr = (const ulonglong2*)(Gs + k * F);
#pragma unroll
        for (int q = 0; q < 8; q++) {
            ulonglong2 a = gr[q];
            tt[2*q+0] = ffma2(xk2, a.x, tt[2*q+0]);
            tt[2*q+1] = ffma2(xk2, a.y, tt[2*q+1]);
        }
    }
    // diag = tt.x + x.v + c
    u64 d1 = 0ull, d2 = 0ull;
#pragma unroll
    for (int i = 0; i < 16; i++) {
        const u64 x2 = pk2(xv[2*i+0], xv[2*i+1]);
        d1 = ffma2(tt[i], x2, d1);
        d2 = ffma2(((const u64*)vs)[i], x2, d2);
    }
    float2 e1 = up2(d1), e2 = up2(d2);
    const float diag = e1.x + e1.y + e2.x + e2.y + cshared;

    // ---- pass 2: o = b3 + x@M3, then o += x ----
    u64 o[16];
#pragma unroll
    for (int i = 0; i < 16; i++) o[i] = ((const u64*)b3s)[i];
#pragma unroll
    for (int k = 0; k < F; k++) {
        const u64 xk2 = pk2(xv[k], xv[k]);
        const ulonglong2* mr = (const ulonglong2*)(m3s + k * F);
#pragma unroll
        for (int q = 0; q < 8; q++) {
            ulonglong2 a = mr[q];
            o[2*q+0] = ffma2(xk2, a.x, o[2*q+0]);
            o[2*q+1] = ffma2(xk2, a.y, o[2*q+1]);
        }
    }
#pragma unroll
    for (int i = 0; i < 16; i++)
        o[i] = add2(o[i], pk2(xv[2*i+0], xv[2*i+1]));   // residual; xv dies

    // ---- pass 3: uw = u @ w_r, halves to cap registers ----
    float uu[F];
#pragma unroll
    for (int i = 0; i < 8; i++) {
        float4 v = ((const float4*)(g_u + gx))[i];
        uu[4*i+0] = v.x; uu[4*i+1] = v.y; uu[4*i+2] = v.z; uu[4*i+3] = v.w;
    }
    const float s = diag * INV_N;
    const u64 ns2 = pk2(-s, -s);
#pragma unroll
    for (int hf = 0; hf < 2; hf++) {
        u64 uw[8];
#pragma unroll
        for (int i = 0; i < 8; i++) uw[i] = 0ull;
#pragma unroll
        for (int k = 0; k < F; k++) {
            const u64 uk2 = pk2(uu[k], uu[k]);
            const ulonglong2* wr = (const ulonglong2*)(wrs + k * F + hf * 16);
            ulonglong2 a0 = wr[0], a1 = wr[1];
            uw[0] = ffma2(uk2, a0.x, uw[0]);
            uw[1] = ffma2(uk2, a0.y, uw[1]);
            uw[2] = ffma2(uk2, a1.x, uw[2]);
            uw[3] = ffma2(uk2, a1.y, uw[3]);
            const ulonglong2* wr2 = (const ulonglong2*)(wrs + k * F + hf * 16 + 8);
            ulonglong2 b0 = wr2[0], b1 = wr2[1];
            uw[4] = ffma2(uk2, b0.x, uw[4]);
            uw[5] = ffma2(uk2, b0.y, uw[5]);
            uw[6] = ffma2(uk2, b1.x, uw[6]);
            uw[7] = ffma2(uk2, b1.y, uw[7]);
        }
#pragma unroll
        for (int i = 0; i < 8; i++)
            o[hf * 8 + i] = ffma2(ns2, uw[i], o[hf * 8 + i]);
    }

    // ---- store ----
#pragma unroll
    for (int q = 0; q < 8; q++) {
        float2 lo = up2(o[2*q+0]), hi = up2(o[2*q+1]);
        ((float4*)(out + gx))[q] = make_float4(lo.x, lo.y, hi.x, hi.y);
    }
}

// ---------------------------------------------------------------------------
extern "C" void kernel_launch(void* const* d_in, const int* in_sizes, int n_in,
                              void* d_out, int out_size)
{
    const float* x     = (const float*)d_in[0];
    const float* w_psi = (const float*)d_in[1];
    const float* b_psi = (const float*)d_in[2];
    const float* w_phi = (const float*)d_in[3];
    const float* b_phi = (const float*)d_in[4];
    const float* w_u   = (const float*)d_in[5];
    const float* b_u   = (const float*)d_in[6];
    const float* w_r   = (const float*)d_in[7];
    float* out = (float*)d_out;

    k_pre<<<1, 256>>>(w_psi, b_psi, w_phi, b_phi);
    dim3 g1(BATCH, SPLITS);
    k_partialM<<<g1, 128>>>(x, w_phi, b_phi, w_u, b_u);
    k_reduceM<<<BATCH, 256>>>(w_r, w_psi, b_psi);
    k_main<<<BATCH * 16, 128>>>(x, w_r, out);
}